// round 1
// baseline (speedup 1.0000x reference)
#include <cuda_runtime.h>

// Problem dims
#define NB  4
#define NSQ 512
#define NSK 512
#define ND  512
#define NS  128

// Tiling
#define TQ  16     // q rows per attention block
#define KT  128    // k tile in attention kernel
#define KMP 132    // km smem row pad (floats): 4*kk mod 32 -> conflict-free LDS.128
#define SCP 20     // scores_T row pad (floats): 16B-aligned rows, modest conflicts only in softmax

// Scratch (allocation-free: __device__ globals)
__device__ __align__(16) float g_Wqh[ND * NS];
__device__ __align__(16) float g_Wkh[ND * NS];
__device__ __align__(16) float g_cA[NS];
__device__ __align__(16) float g_cK[NS];
__device__ __align__(16) float g_A[NB * NSQ * NS];   // qh + (bq@W1a + b1)
__device__ __align__(16) float g_K[NB * NSK * NS];   // kh + (bk@W1b)

// ---------------------------------------------------------------------------
// Kernel 1: fold linear layers.  Wqh = Wq @ W1[:S], Wkh = Wk @ W1[S:]
// grid (ND, 2), block NS
// ---------------------------------------------------------------------------
__global__ void fold_weights_kernel(const float* __restrict__ Wq,
                                    const float* __restrict__ Wk,
                                    const float* __restrict__ W1) {
    int d = blockIdx.x;
    int v = blockIdx.y;
    int s = threadIdx.x;
    __shared__ float wrow[NS];
    const float* Wsrc = v ? Wk : Wq;
    wrow[s] = Wsrc[d * NS + s];
    __syncthreads();
    const float* W1p = W1 + (v ? NS * NS : 0);
    float acc = 0.f;
#pragma unroll 8
    for (int t = 0; t < NS; t++) acc = fmaf(wrow[t], W1p[t * NS + s], acc);
    (v ? g_Wkh : g_Wqh)[d * NS + s] = acc;
}

// cA[s] = b1[s] + (bq @ W1[:S])[s];  cK[s] = (bk @ W1[S:])[s]
__global__ void fold_bias_kernel(const float* __restrict__ bq,
                                 const float* __restrict__ bk,
                                 const float* __restrict__ W1,
                                 const float* __restrict__ b1) {
    int s = threadIdx.x;
    float a = b1[s], c = 0.f;
    for (int t = 0; t < NS; t++) {
        a = fmaf(bq[t], W1[t * NS + s], a);
        c = fmaf(bk[t], W1[(NS + t) * NS + s], c);
    }
    g_cA[s] = a;
    g_cK[s] = c;
}

// ---------------------------------------------------------------------------
// Kernel 2: projection GEMMs.  g_A = query @ g_Wqh + cA ; g_K = key @ g_Wkh + cK
// M = NB*NSQ = 2048, K = 512, N = 128.  BM=64, BN=64, BK=16, 256 thr, 4x4/thr.
// grid (32, 2, 2)
// ---------------------------------------------------------------------------
#define BM 64
#define BN 64
#define BKK 16

__global__ __launch_bounds__(256) void proj_gemm_kernel(
        const float* __restrict__ Xq, const float* __restrict__ Xk) {
    int v = blockIdx.z;
    const float* X = v ? Xk : Xq;
    const float* W = v ? g_Wkh : g_Wqh;
    const float* c = v ? g_cK : g_cA;
    float* O       = v ? g_K : g_A;

    int m0 = blockIdx.x * BM;
    int n0 = blockIdx.y * BN;
    int tid = threadIdx.x;
    int tx = tid & 15, ty = tid >> 4;

    __shared__ float As[BM][BKK + 1];
    __shared__ float Bs[BKK][BN];

    float acc[4][4] = {};

    for (int k0 = 0; k0 < ND; k0 += BKK) {
        {   // load A tile: 64 rows x 16 cols
            int r = tid >> 2, c4 = (tid & 3) * 4;
            float4 va = *(const float4*)&X[(m0 + r) * ND + k0 + c4];
            As[r][c4 + 0] = va.x; As[r][c4 + 1] = va.y;
            As[r][c4 + 2] = va.z; As[r][c4 + 3] = va.w;
        }
        {   // load B tile: 16 rows x 64 cols
            int r = tid >> 4, cc = (tid & 15) * 4;
            *(float4*)&Bs[r][cc] = *(const float4*)&W[(k0 + r) * NS + n0 + cc];
        }
        __syncthreads();
#pragma unroll
        for (int kk = 0; kk < BKK; kk++) {
            float a0 = As[ty * 4 + 0][kk];
            float a1 = As[ty * 4 + 1][kk];
            float a2 = As[ty * 4 + 2][kk];
            float a3 = As[ty * 4 + 3][kk];
            float4 bv = *(float4*)&Bs[kk][tx * 4];
            acc[0][0] = fmaf(a0, bv.x, acc[0][0]); acc[0][1] = fmaf(a0, bv.y, acc[0][1]);
            acc[0][2] = fmaf(a0, bv.z, acc[0][2]); acc[0][3] = fmaf(a0, bv.w, acc[0][3]);
            acc[1][0] = fmaf(a1, bv.x, acc[1][0]); acc[1][1] = fmaf(a1, bv.y, acc[1][1]);
            acc[1][2] = fmaf(a1, bv.z, acc[1][2]); acc[1][3] = fmaf(a1, bv.w, acc[1][3]);
            acc[2][0] = fmaf(a2, bv.x, acc[2][0]); acc[2][1] = fmaf(a2, bv.y, acc[2][1]);
            acc[2][2] = fmaf(a2, bv.z, acc[2][2]); acc[2][3] = fmaf(a2, bv.w, acc[2][3]);
            acc[3][0] = fmaf(a3, bv.x, acc[3][0]); acc[3][1] = fmaf(a3, bv.y, acc[3][1]);
            acc[3][2] = fmaf(a3, bv.z, acc[3][2]); acc[3][3] = fmaf(a3, bv.w, acc[3][3]);
        }
        __syncthreads();
    }

    float4 cb = *(const float4*)&c[n0 + tx * 4];
#pragma unroll
    for (int i = 0; i < 4; i++) {
        int row = m0 + ty * 4 + i;
        float4 r;
        r.x = acc[i][0] + cb.x; r.y = acc[i][1] + cb.y;
        r.z = acc[i][2] + cb.z; r.w = acc[i][3] + cb.w;
        *(float4*)&O[row * NS + n0 + tx * 4] = r;
    }
}

// ---------------------------------------------------------------------------
// Kernel 3: fused scores -> softmax -> attn write -> attn @ V
// grid: NB*NSQ/TQ = 128 blocks, 256 threads, ~117 KB dynamic smem
// ---------------------------------------------------------------------------
__global__ __launch_bounds__(256) void attn_fused_kernel(
        const float* __restrict__ Vv, const int* __restrict__ mask,
        const float* __restrict__ W2, const float* __restrict__ b2,
        float* __restrict__ out, float* __restrict__ attn_out, int write_attn) {
    extern __shared__ float sm[];
    float* qcs = sm;                       // TQ*NS        = 2048 f
    float* w2s = qcs + TQ * NS;            // NS           = 128 f
    float* scT = w2s + NS;                 // NSK*SCP      = 10240 f
    float* kms = scT + NSK * SCP;          // KT*KMP       = 16896 f

    int bx  = blockIdx.x;
    int b   = bx >> 5;                     // 32 q-tiles per batch
    int q0  = (bx & 31) * TQ;
    int tid = threadIdx.x;

    // stage q-context rows and w2
    const float4* A4 = (const float4*)&g_A[(b * NSQ + q0) * NS];
    for (int i = tid; i < TQ * NS / 4; i += 256) ((float4*)qcs)[i] = A4[i];
    if (tid < NS / 4) ((float4*)w2s)[tid] = ((const float4*)W2)[tid];
    float b2v = b2[0];

    // ---- phase 1: scores ----
    int kk  = tid & 127;
    int qh8 = (tid >> 7) * 8;              // this thread handles q rows qh8..qh8+7

    for (int k0 = 0; k0 < NSK; k0 += KT) {
        __syncthreads();                   // protect kms reuse (and initial qcs stage)
        const float4* K4 = (const float4*)&g_K[(b * NSK + k0) * NS];
        for (int i = tid; i < KT * NS / 4; i += 256) {
            int kr = i >> 5;               // NS/4 = 32 float4 per row
            int s4 = i & 31;
            *(float4*)&kms[kr * KMP + s4 * 4] = K4[kr * 32 + s4];
        }
        __syncthreads();

        float acc[8] = {0, 0, 0, 0, 0, 0, 0, 0};
#pragma unroll 8
        for (int s = 0; s < NS; s += 4) {
            float4 kv = *(float4*)&kms[kk * KMP + s];
            float4 wv = *(float4*)&w2s[s];
#pragma unroll
            for (int j = 0; j < 8; j++) {
                float4 qv = *(float4*)&qcs[(qh8 + j) * NS + s];
                float x0 = fmaxf(qv.x + kv.x, 0.f);
                float x1 = fmaxf(qv.y + kv.y, 0.f);
                float x2 = fmaxf(qv.z + kv.z, 0.f);
                float x3 = fmaxf(qv.w + kv.w, 0.f);
                acc[j] = fmaf(x0, wv.x, acc[j]);
                acc[j] = fmaf(x1, wv.y, acc[j]);
                acc[j] = fmaf(x2, wv.z, acc[j]);
                acc[j] = fmaf(x3, wv.w, acc[j]);
            }
        }
        int kg = k0 + kk;
#pragma unroll
        for (int j = 0; j < 8; j++) {
            int q = qh8 + j;
            float sc = acc[j] + b2v;
            int m = mask[(b * NSQ + q0 + q) * NSK + kg];
            scT[kg * SCP + q] = (m == 0) ? -1e9f : sc;
        }
    }
    __syncthreads();

    // ---- phase 2: softmax (warp w handles q = 2w, 2w+1) ----
    {
        int w = tid >> 5, lane = tid & 31;
#pragma unroll
        for (int qq = 0; qq < 2; qq++) {
            int q = w * 2 + qq;
            float vals[16];
            float mx = -3.0e38f;
#pragma unroll
            for (int j = 0; j < 16; j++) {
                vals[j] = scT[(lane + j * 32) * SCP + q];
                mx = fmaxf(mx, vals[j]);
            }
#pragma unroll
            for (int o = 16; o; o >>= 1) mx = fmaxf(mx, __shfl_xor_sync(0xffffffffu, mx, o));
            float sum = 0.f;
#pragma unroll
            for (int j = 0; j < 16; j++) {
                float e = __expf(vals[j] - mx);
                vals[j] = e;
                sum += e;
            }
#pragma unroll
            for (int o = 16; o; o >>= 1) sum += __shfl_xor_sync(0xffffffffu, sum, o);
            float inv = 1.0f / sum;
#pragma unroll
            for (int j = 0; j < 16; j++) scT[(lane + j * 32) * SCP + q] = vals[j] * inv;
        }
    }
    __syncthreads();

    // ---- write attn output (tuple element 1) ----
    if (write_attn) {
        for (int i = tid; i < TQ * NSK; i += 256) {
            int q = i >> 9;                // / 512
            int k = i & 511;
            attn_out[(b * NSQ + q0 + q) * NSK + k] = scT[k * SCP + q];
        }
    }

    // ---- phase 3: out = attn @ V  (thread owns 2 d columns across 16 q) ----
    float o0[TQ] = {}, o1[TQ] = {};
    int d0 = tid, d1 = tid + 256;
    const float* Vb = Vv + b * NSK * ND;
#pragma unroll 4
    for (int k = 0; k < NSK; k++) {
        float v0 = Vb[k * ND + d0];
        float v1 = Vb[k * ND + d1];
#pragma unroll
        for (int qg = 0; qg < 4; qg++) {
            float4 a4 = *(float4*)&scT[k * SCP + qg * 4];
            o0[qg * 4 + 0] = fmaf(a4.x, v0, o0[qg * 4 + 0]);
            o1[qg * 4 + 0] = fmaf(a4.x, v1, o1[qg * 4 + 0]);
            o0[qg * 4 + 1] = fmaf(a4.y, v0, o0[qg * 4 + 1]);
            o1[qg * 4 + 1] = fmaf(a4.y, v1, o1[qg * 4 + 1]);
            o0[qg * 4 + 2] = fmaf(a4.z, v0, o0[qg * 4 + 2]);
            o1[qg * 4 + 2] = fmaf(a4.z, v1, o1[qg * 4 + 2]);
            o0[qg * 4 + 3] = fmaf(a4.w, v0, o0[qg * 4 + 3]);
            o1[qg * 4 + 3] = fmaf(a4.w, v1, o1[qg * 4 + 3]);
        }
    }
#pragma unroll
    for (int q = 0; q < TQ; q++) {
        out[(b * NSQ + q0 + q) * ND + d0] = o0[q];
        out[(b * NSQ + q0 + q) * ND + d1] = o1[q];
    }
}

// ---------------------------------------------------------------------------
#define SMEM_C ((TQ * NS + NS + NSK * SCP + KT * KMP) * 4)

extern "C" void kernel_launch(void* const* d_in, const int* in_sizes, int n_in,
                              void* d_out, int out_size) {
    const float* query = (const float*)d_in[0];
    const float* key   = (const float*)d_in[1];
    const float* value = (const float*)d_in[2];
    const int*   mask  = (const int*)d_in[3];
    const float* Wq = (const float*)d_in[4];
    const float* bq = (const float*)d_in[5];
    const float* Wk = (const float*)d_in[6];
    const float* bk = (const float*)d_in[7];
    const float* W1 = (const float*)d_in[8];
    const float* b1 = (const float*)d_in[9];
    const float* W2 = (const float*)d_in[10];
    const float* b2 = (const float*)d_in[11];

    float* out  = (float*)d_out;
    float* attn = out + NB * NSQ * ND;
    int write_attn = (out_size >= NB * NSQ * ND + NB * NSQ * NSK) ? 1 : 0;

    cudaFuncSetAttribute(attn_fused_kernel,
                         cudaFuncAttributeMaxDynamicSharedMemorySize, SMEM_C);

    fold_weights_kernel<<<dim3(ND, 2), NS>>>(Wq, Wk, W1);
    fold_bias_kernel<<<1, NS>>>(bq, bk, W1, b1);
    proj_gemm_kernel<<<dim3((NB * NSQ) / BM, NS / BN, 2), 256>>>(query, key);
    attn_fused_kernel<<<(NB * NSQ) / TQ, 256, SMEM_C>>>(
        value, mask, W2, b2, out, attn, write_attn);
}